// round 2
// baseline (speedup 1.0000x reference)
#include <cuda_runtime.h>

#define N_NODES 65536
#define N_EDGES 1048576
#define DIM 64

// ---------------- scratch (static device allocations; no cudaMalloc) ----------
__device__ int   g_deg_out[N_NODES];
__device__ int   g_deg_in [N_NODES];
__device__ float g_rs_out [N_NODES];
__device__ float g_rs_in  [N_NODES];
__device__ int   g_row_off[N_NODES + 1];
__device__ int   g_cursor [N_NODES];
__device__ int   g_csr_src[N_EDGES];
__device__ float g_T[N_NODES * DIM];   // post-GEMM, pre-scatter buffer
__device__ float g_H[N_NODES * DIM];   // inter-layer hidden buffer

// ---------------- setup kernels ----------------------------------------------
__global__ void zero_kernel() {
    int i = blockIdx.x * blockDim.x + threadIdx.x;
    if (i < N_NODES) { g_deg_out[i] = 0; g_deg_in[i] = 0; g_cursor[i] = 0; }
}

__global__ void deg_kernel(const int* __restrict__ ei) {
    int e = blockIdx.x * blockDim.x + threadIdx.x;
    if (e < N_EDGES) {
        atomicAdd(&g_deg_out[ei[e]], 1);
        atomicAdd(&g_deg_in [ei[N_EDGES + e]], 1);
    }
}

__global__ void rs_kernel() {
    int i = blockIdx.x * blockDim.x + threadIdx.x;
    if (i < N_NODES) {
        g_rs_out[i] = rsqrtf(fmaxf((float)g_deg_out[i], 1.0f));
        g_rs_in [i] = rsqrtf(fmaxf((float)g_deg_in [i], 1.0f));
    }
}

// Single-block exclusive scan of deg_in -> row offsets (65536 = 1024 threads x 64)
__global__ void scan_kernel() {
    __shared__ int sums[1024];
    int t = threadIdx.x;
    int base = t * 64;
    int s = 0;
#pragma unroll
    for (int i = 0; i < 64; i++) { g_row_off[base + i] = s; s += g_deg_in[base + i]; }
    sums[t] = s;
    __syncthreads();
    for (int off = 1; off < 1024; off <<= 1) {
        int v = (t >= off) ? sums[t - off] : 0;
        __syncthreads();
        sums[t] += v;
        __syncthreads();
    }
    int offs = (t == 0) ? 0 : sums[t - 1];
#pragma unroll
    for (int i = 0; i < 64; i++) g_row_off[base + i] += offs;
    if (t == 1023) g_row_off[N_NODES] = sums[1023];
}

__global__ void fill_kernel(const int* __restrict__ ei) {
    int e = blockIdx.x * blockDim.x + threadIdx.x;
    if (e < N_EDGES) {
        int d = ei[N_EDGES + e];
        int p = atomicAdd(&g_cursor[d], 1);
        g_csr_src[g_row_off[d] + p] = ei[e];
    }
}

// ---------------- per-layer kernels -------------------------------------------
// t[n,:] = (x[n,:] @ W) * rs_out[n]     (warp per row, W staged in smem)
__global__ void gemm_kernel(const float* __restrict__ x,
                            const float* __restrict__ W,
                            float* __restrict__ out) {
    __shared__ float Ws[DIM * DIM];
    int tid = threadIdx.x;
#pragma unroll
    for (int i = tid; i < DIM * DIM; i += 256) Ws[i] = W[i];
    __syncthreads();

    int gw   = (blockIdx.x * 256 + tid) >> 5;   // global warp id = row
    int lane = tid & 31;
    if (gw >= N_NODES) return;

    const float* xr = x + gw * DIM;
    float a0 = 0.f, a1 = 0.f;
#pragma unroll
    for (int k = 0; k < DIM; k++) {
        float xv = __ldg(&xr[k]);                              // warp-broadcast load
        float2 w = *(const float2*)&Ws[k * DIM + lane * 2];    // LDS.64, conflict-free
        a0 = fmaf(xv, w.x, a0);
        a1 = fmaf(xv, w.y, a1);
    }
    float s = g_rs_out[gw];
    *(float2*)&out[gw * DIM + lane * 2] = make_float2(a0 * s, a1 * s);
}

// out[n,:] = act( rs_in[n] * sum_{e in CSR[n]} t[src_e,:] + b )   (warp per node)
__global__ void agg_kernel(const float* __restrict__ t,
                           const float* __restrict__ bias,
                           float* __restrict__ out, int relu) {
    int tid  = threadIdx.x;
    int gw   = (blockIdx.x * 256 + tid) >> 5;
    int lane = tid & 31;
    if (gw >= N_NODES) return;

    int beg = g_row_off[gw], end = g_row_off[gw + 1];
    float a0 = 0.f, a1 = 0.f;
    int e = beg;
    for (; e + 4 <= end; e += 4) {                 // 4-way unroll for MLP
        int s0 = g_csr_src[e];
        int s1 = g_csr_src[e + 1];
        int s2 = g_csr_src[e + 2];
        int s3 = g_csr_src[e + 3];
        float2 v0 = *(const float2*)&t[s0 * DIM + lane * 2];
        float2 v1 = *(const float2*)&t[s1 * DIM + lane * 2];
        float2 v2 = *(const float2*)&t[s2 * DIM + lane * 2];
        float2 v3 = *(const float2*)&t[s3 * DIM + lane * 2];
        a0 += (v0.x + v1.x) + (v2.x + v3.x);
        a1 += (v0.y + v1.y) + (v2.y + v3.y);
    }
    for (; e < end; e++) {
        int s0 = g_csr_src[e];
        float2 v = *(const float2*)&t[s0 * DIM + lane * 2];
        a0 += v.x; a1 += v.y;
    }
    float sc = g_rs_in[gw];
    float2 bb = *(const float2*)&bias[lane * 2];
    float o0 = fmaf(a0, sc, bb.x);
    float o1 = fmaf(a1, sc, bb.y);
    if (relu) { o0 = fmaxf(o0, 0.f); o1 = fmaxf(o1, 0.f); }
    *(float2*)&out[gw * DIM + lane * 2] = make_float2(o0, o1);
}

// ---------------- launch ------------------------------------------------------
extern "C" void kernel_launch(void* const* d_in, const int* in_sizes, int n_in,
                              void* d_out, int out_size) {
    const float* x  = (const float*)d_in[0];
    const int*   ei = (const int*)  d_in[1];   // [2, E]: src row then dst row
    // d_in[2] = batch_num_nodes (16 equal graphs, contiguous -> output is flat h)
    const float* W1 = (const float*)d_in[3];
    const float* b1 = (const float*)d_in[4];
    const float* W2 = (const float*)d_in[5];
    const float* b2 = (const float*)d_in[6];
    const float* W3 = (const float*)d_in[7];
    const float* b3 = (const float*)d_in[8];
    float* out = (float*)d_out;

    void *pT = nullptr, *pH = nullptr;
    cudaGetSymbolAddress(&pT, g_T);
    cudaGetSymbolAddress(&pH, g_H);
    float* T = (float*)pT;
    float* H = (float*)pH;

    const int nb_nodes = (N_NODES + 255) / 256;
    const int nb_edges = (N_EDGES + 255) / 256;
    const int nb_warp  = (N_NODES * 32 + 255) / 256;   // warp per node

    zero_kernel<<<nb_nodes, 256>>>();
    deg_kernel <<<nb_edges, 256>>>(ei);
    rs_kernel  <<<nb_nodes, 256>>>();
    scan_kernel<<<1, 1024>>>();
    fill_kernel<<<nb_edges, 256>>>(ei);

    // layer 1
    gemm_kernel<<<nb_warp, 256>>>(x, W1, T);
    agg_kernel <<<nb_warp, 256>>>(T, b1, H, 1);
    // layer 2
    gemm_kernel<<<nb_warp, 256>>>(H, W2, T);
    agg_kernel <<<nb_warp, 256>>>(T, b2, H, 1);
    // layer 3 (no relu), write straight to d_out (unbatch == flat copy)
    gemm_kernel<<<nb_warp, 256>>>(H, W3, T);
    agg_kernel <<<nb_warp, 256>>>(T, b3, out, 0);
}

// round 3
// speedup vs baseline: 1.6005x; 1.6005x over previous
#include <cuda_runtime.h>

#define N_NODES 65536
#define N_EDGES 1048576
#define DIM 64
#define SCAN_BLOCKS 64   // 64 blocks x 1024 threads = 65536

// ---------------- scratch (static device allocations; no cudaMalloc) ----------
__device__ int   g_deg_out[N_NODES];
__device__ int   g_deg_in [N_NODES];
__device__ float g_rs_out [N_NODES];
__device__ float g_rs_in  [N_NODES];
__device__ int   g_row_off[N_NODES + 1];
__device__ int   g_cursor [N_NODES];
__device__ int   g_blk    [SCAN_BLOCKS];
__device__ int   g_csr_src[N_EDGES];
__device__ float g_T[N_NODES * DIM];   // post-GEMM, pre-scatter buffer
__device__ float g_H[N_NODES * DIM];   // inter-layer hidden buffer

// ---------------- setup kernels ----------------------------------------------
__global__ void zero_kernel() {
    int i = blockIdx.x * blockDim.x + threadIdx.x;
    if (i < N_NODES) { g_deg_out[i] = 0; g_deg_in[i] = 0; g_cursor[i] = 0; }
}

__global__ void deg_kernel(const int* __restrict__ ei) {
    int e = blockIdx.x * blockDim.x + threadIdx.x;
    if (e < N_EDGES) {
        atomicAdd(&g_deg_out[ei[e]], 1);
        atomicAdd(&g_deg_in [ei[N_EDGES + e]], 1);
    }
}

// -------- 3-stage parallel exclusive scan of g_deg_in -> g_row_off ------------
// S1: block-local scan (1024 elems/block), write local-exclusive + block total
__global__ void scan1_kernel() {
    __shared__ int sm[1024];
    int t   = threadIdx.x;
    int gid = blockIdx.x * 1024 + t;
    int v = g_deg_in[gid];
    sm[t] = v;
    __syncthreads();
#pragma unroll
    for (int off = 1; off < 1024; off <<= 1) {
        int u = (t >= off) ? sm[t - off] : 0;
        __syncthreads();
        sm[t] += u;
        __syncthreads();
    }
    g_row_off[gid] = sm[t] - v;               // local exclusive prefix
    if (t == 1023) g_blk[blockIdx.x] = sm[1023];
}

// S2: scan the 64 block totals (exclusive), write grand total to row_off[N]
__global__ void scan2_kernel() {
    __shared__ int sm[SCAN_BLOCKS];
    int t = threadIdx.x;
    int v = g_blk[t];
    sm[t] = v;
    __syncthreads();
#pragma unroll
    for (int off = 1; off < SCAN_BLOCKS; off <<= 1) {
        int u = (t >= off) ? sm[t - off] : 0;
        __syncthreads();
        sm[t] += u;
        __syncthreads();
    }
    g_blk[t] = sm[t] - v;                     // exclusive block offsets
    if (t == SCAN_BLOCKS - 1) g_row_off[N_NODES] = sm[SCAN_BLOCKS - 1];
}

// S3: add block offset; fuse rsqrt factor computation (replaces rs_kernel)
__global__ void scan3_kernel() {
    int gid = blockIdx.x * 1024 + threadIdx.x;
    g_row_off[gid] += g_blk[blockIdx.x];
    g_rs_out[gid] = rsqrtf(fmaxf((float)g_deg_out[gid], 1.0f));
    g_rs_in [gid] = rsqrtf(fmaxf((float)g_deg_in [gid], 1.0f));
}

__global__ void fill_kernel(const int* __restrict__ ei) {
    int e = blockIdx.x * blockDim.x + threadIdx.x;
    if (e < N_EDGES) {
        int d = ei[N_EDGES + e];
        int p = atomicAdd(&g_cursor[d], 1);
        g_csr_src[g_row_off[d] + p] = ei[e];
    }
}

// ---------------- per-layer kernels -------------------------------------------
// t[n,:] = (x[n,:] @ W) * rs_out[n]     (warp per row, W staged in smem)
__global__ void gemm_kernel(const float* __restrict__ x,
                            const float* __restrict__ W,
                            float* __restrict__ out) {
    __shared__ float Ws[DIM * DIM];
    int tid = threadIdx.x;
#pragma unroll
    for (int i = tid; i < DIM * DIM; i += 256) Ws[i] = W[i];
    __syncthreads();

    int gw   = (blockIdx.x * 256 + tid) >> 5;   // global warp id = row
    int lane = tid & 31;
    if (gw >= N_NODES) return;

    const float* xr = x + gw * DIM;
    float a0 = 0.f, a1 = 0.f;
#pragma unroll
    for (int k = 0; k < DIM; k++) {
        float xv = __ldg(&xr[k]);                              // warp-broadcast load
        float2 w = *(const float2*)&Ws[k * DIM + lane * 2];    // LDS.64, conflict-free
        a0 = fmaf(xv, w.x, a0);
        a1 = fmaf(xv, w.y, a1);
    }
    float s = g_rs_out[gw];
    *(float2*)&out[gw * DIM + lane * 2] = make_float2(a0 * s, a1 * s);
}

// out[n,:] = act( rs_in[n] * sum_{e in CSR[n]} t[src_e,:] + b )   (warp per node)
__global__ void agg_kernel(const float* __restrict__ t,
                           const float* __restrict__ bias,
                           float* __restrict__ out, int relu) {
    int tid  = threadIdx.x;
    int gw   = (blockIdx.x * 256 + tid) >> 5;
    int lane = tid & 31;
    if (gw >= N_NODES) return;

    int beg = g_row_off[gw], end = g_row_off[gw + 1];
    float a0 = 0.f, a1 = 0.f;
    int e = beg;
    for (; e + 4 <= end; e += 4) {                 // 4-way unroll for MLP
        int s0 = g_csr_src[e];
        int s1 = g_csr_src[e + 1];
        int s2 = g_csr_src[e + 2];
        int s3 = g_csr_src[e + 3];
        float2 v0 = *(const float2*)&t[s0 * DIM + lane * 2];
        float2 v1 = *(const float2*)&t[s1 * DIM + lane * 2];
        float2 v2 = *(const float2*)&t[s2 * DIM + lane * 2];
        float2 v3 = *(const float2*)&t[s3 * DIM + lane * 2];
        a0 += (v0.x + v1.x) + (v2.x + v3.x);
        a1 += (v0.y + v1.y) + (v2.y + v3.y);
    }
    for (; e < end; e++) {
        int s0 = g_csr_src[e];
        float2 v = *(const float2*)&t[s0 * DIM + lane * 2];
        a0 += v.x; a1 += v.y;
    }
    float sc = g_rs_in[gw];
    float2 bb = *(const float2*)&bias[lane * 2];
    float o0 = fmaf(a0, sc, bb.x);
    float o1 = fmaf(a1, sc, bb.y);
    if (relu) { o0 = fmaxf(o0, 0.f); o1 = fmaxf(o1, 0.f); }
    *(float2*)&out[gw * DIM + lane * 2] = make_float2(o0, o1);
}

// ---------------- launch ------------------------------------------------------
extern "C" void kernel_launch(void* const* d_in, const int* in_sizes, int n_in,
                              void* d_out, int out_size) {
    const float* x  = (const float*)d_in[0];
    const int*   ei = (const int*)  d_in[1];   // [2, E]: src row then dst row
    // d_in[2] = batch_num_nodes (16 equal graphs, contiguous -> output is flat h)
    const float* W1 = (const float*)d_in[3];
    const float* b1 = (const float*)d_in[4];
    const float* W2 = (const float*)d_in[5];
    const float* b2 = (const float*)d_in[6];
    const float* W3 = (const float*)d_in[7];
    const float* b3 = (const float*)d_in[8];
    float* out = (float*)d_out;

    void *pT = nullptr, *pH = nullptr;
    cudaGetSymbolAddress(&pT, g_T);
    cudaGetSymbolAddress(&pH, g_H);
    float* T = (float*)pT;
    float* H = (float*)pH;

    const int nb_nodes = (N_NODES + 255) / 256;
    const int nb_edges = (N_EDGES + 255) / 256;
    const int nb_warp  = (N_NODES * 32 + 255) / 256;   // warp per node

    zero_kernel <<<nb_nodes, 256>>>();
    deg_kernel  <<<nb_edges, 256>>>(ei);
    scan1_kernel<<<SCAN_BLOCKS, 1024>>>();
    scan2_kernel<<<1, SCAN_BLOCKS>>>();
    scan3_kernel<<<SCAN_BLOCKS, 1024>>>();
    fill_kernel <<<nb_edges, 256>>>(ei);

    // layer 1
    gemm_kernel<<<nb_warp, 256>>>(x, W1, T);
    agg_kernel <<<nb_warp, 256>>>(T, b1, H, 1);
    // layer 2
    gemm_kernel<<<nb_warp, 256>>>(H, W2, T);
    agg_kernel <<<nb_warp, 256>>>(T, b2, H, 1);
    // layer 3 (no relu), write straight to d_out (unbatch == flat copy)
    gemm_kernel<<<nb_warp, 256>>>(H, W3, T);
    agg_kernel <<<nb_warp, 256>>>(T, b3, out, 0);
}

// round 4
// speedup vs baseline: 2.2342x; 1.3960x over previous
#include <cuda_runtime.h>

#define N_NODES 65536
#define N_EDGES 1048576
#define DIM 64
#define SCAN_BLOCKS 64   // 64 blocks x 1024 threads = 65536

// ---------------- scratch (static device allocations; no cudaMalloc) ----------
__device__ int   g_deg_out[N_NODES];
__device__ int   g_deg_in [N_NODES];
__device__ float g_rs_out [N_NODES];
__device__ float g_rs_in  [N_NODES];
__device__ int   g_row_off[N_NODES + 1];
__device__ int   g_cursor [N_NODES];
__device__ int   g_blk    [SCAN_BLOCKS];
__device__ int   g_csr_src[N_EDGES];
__device__ float g_T[N_NODES * DIM];   // post-GEMM, pre-scatter buffer
__device__ float g_H[N_NODES * DIM];   // inter-layer hidden buffer

// ---------------- setup kernels ----------------------------------------------
__global__ void zero_kernel() {
    int i = blockIdx.x * blockDim.x + threadIdx.x;
    if (i < N_NODES) { g_deg_out[i] = 0; g_deg_in[i] = 0; }
}

__global__ void deg_kernel(const int* __restrict__ ei) {
    int e = blockIdx.x * blockDim.x + threadIdx.x;
    if (e < N_EDGES) {
        atomicAdd(&g_deg_out[ei[e]], 1);
        atomicAdd(&g_deg_in [ei[N_EDGES + e]], 1);
    }
}

// -------- parallel exclusive scan of g_deg_in -> g_row_off --------------------
// S1: block-local scan (1024 elems/block), write local-exclusive + block total
__global__ void scan1_kernel() {
    __shared__ int sm[1024];
    int t   = threadIdx.x;
    int gid = blockIdx.x * 1024 + t;
    int v = g_deg_in[gid];
    sm[t] = v;
    __syncthreads();
#pragma unroll
    for (int off = 1; off < 1024; off <<= 1) {
        int u = (t >= off) ? sm[t - off] : 0;
        __syncthreads();
        sm[t] += u;
        __syncthreads();
    }
    g_row_off[gid] = sm[t] - v;               // local exclusive prefix
    if (t == 1023) g_blk[blockIdx.x] = sm[1023];
}

// S2+S3 fused: each block derives its own offset from the 64 totals,
// finalizes row_off, seeds cursor, computes rsqrt factors.
__global__ void scan3_kernel() {
    __shared__ int off_sh;
    int t = threadIdx.x;
    if (t == 0) {
        int s = 0;
        int b = blockIdx.x;
        for (int i = 0; i < SCAN_BLOCKS; i++) {
            if (i == b) { off_sh = s; break; }
            s += g_blk[i];
        }
        if (b == 0) g_row_off[N_NODES] = N_EDGES;  // grand total is a constant
    }
    __syncthreads();
    int gid = blockIdx.x * 1024 + t;
    int ro = g_row_off[gid] + off_sh;
    g_row_off[gid] = ro;
    g_cursor [gid] = ro;                      // fill uses cursor as write position
    g_rs_out[gid] = rsqrtf(fmaxf((float)g_deg_out[gid], 1.0f));
    g_rs_in [gid] = rsqrtf(fmaxf((float)g_deg_in [gid], 1.0f));
}

__global__ void fill_kernel(const int* __restrict__ ei) {
    int e = blockIdx.x * blockDim.x + threadIdx.x;
    if (e < N_EDGES) {
        int d = ei[N_EDGES + e];
        int p = atomicAdd(&g_cursor[d], 1);   // cursor pre-seeded with row_off
        g_csr_src[p] = ei[e];
    }
}

// ---------------- per-layer kernels -------------------------------------------
// t[n,:] = (x[n,:] @ W) * rs_out[n]
// 256 threads = 8 warps; 4 rows per warp -> 32 rows per block.
// W staged in smem (one LDS.64 per k amortized over 4 rows);
// x staged DUPLICATED as {v,v} so the broadcast operand feeds fma.rn.f32x2 directly.
__global__ void __launch_bounds__(256) gemm_kernel(const float* __restrict__ x,
                                                   const float* __restrict__ W,
                                                   float* __restrict__ out) {
    __shared__ float  Ws[DIM * DIM];       // 16KB
    __shared__ float2 Xs[32 * DIM];        // 16KB (x duplicated per element)
    int tid = threadIdx.x;
    int blockRow = blockIdx.x * 32;

#pragma unroll
    for (int i = tid; i < DIM * DIM; i += 256) Ws[i] = W[i];
#pragma unroll
    for (int i = tid; i < 32 * DIM; i += 256) {
        float v = x[blockRow * DIM + i];
        Xs[i] = make_float2(v, v);
    }
    __syncthreads();

    int warp = tid >> 5, lane = tid & 31;
    int r0 = warp * 4;                     // block-local row base

    const unsigned long long* X0 = (const unsigned long long*)&Xs[(r0 + 0) * DIM];
    const unsigned long long* X1 = (const unsigned long long*)&Xs[(r0 + 1) * DIM];
    const unsigned long long* X2 = (const unsigned long long*)&Xs[(r0 + 2) * DIM];
    const unsigned long long* X3 = (const unsigned long long*)&Xs[(r0 + 3) * DIM];

    unsigned long long a0 = 0ull, a1 = 0ull, a2 = 0ull, a3 = 0ull;
#pragma unroll
    for (int k = 0; k < DIM; k++) {
        unsigned long long w2 =
            *(const unsigned long long*)&Ws[k * DIM + lane * 2];  // LDS.64, conflict-free
        asm("fma.rn.f32x2 %0, %1, %2, %0;" : "+l"(a0) : "l"(X0[k]), "l"(w2));
        asm("fma.rn.f32x2 %0, %1, %2, %0;" : "+l"(a1) : "l"(X1[k]), "l"(w2));
        asm("fma.rn.f32x2 %0, %1, %2, %0;" : "+l"(a2) : "l"(X2[k]), "l"(w2));
        asm("fma.rn.f32x2 %0, %1, %2, %0;" : "+l"(a3) : "l"(X3[k]), "l"(w2));
    }

    int row = blockRow + r0;
    unsigned long long acc[4] = {a0, a1, a2, a3};
#pragma unroll
    for (int r = 0; r < 4; r++) {
        float2 a = *(float2*)&acc[r];
        float s = g_rs_out[row + r];
        *(float2*)&out[(row + r) * DIM + lane * 2] = make_float2(a.x * s, a.y * s);
    }
}

// out[n,:] = act( rs_in[n] * sum_{e in CSR[n]} t[src_e,:] + b )   (warp per node)
__global__ void agg_kernel(const float* __restrict__ t,
                           const float* __restrict__ bias,
                           float* __restrict__ out, int relu) {
    int tid  = threadIdx.x;
    int gw   = (blockIdx.x * 256 + tid) >> 5;
    int lane = tid & 31;
    if (gw >= N_NODES) return;

    int beg = g_row_off[gw], end = g_row_off[gw + 1];
    float a0 = 0.f, a1 = 0.f;
    int e = beg;
    for (; e + 4 <= end; e += 4) {                 // 4-way unroll for MLP
        int s0 = g_csr_src[e];
        int s1 = g_csr_src[e + 1];
        int s2 = g_csr_src[e + 2];
        int s3 = g_csr_src[e + 3];
        float2 v0 = *(const float2*)&t[s0 * DIM + lane * 2];
        float2 v1 = *(const float2*)&t[s1 * DIM + lane * 2];
        float2 v2 = *(const float2*)&t[s2 * DIM + lane * 2];
        float2 v3 = *(const float2*)&t[s3 * DIM + lane * 2];
        a0 += (v0.x + v1.x) + (v2.x + v3.x);
        a1 += (v0.y + v1.y) + (v2.y + v3.y);
    }
    for (; e < end; e++) {
        int s0 = g_csr_src[e];
        float2 v = *(const float2*)&t[s0 * DIM + lane * 2];
        a0 += v.x; a1 += v.y;
    }
    float sc = g_rs_in[gw];
    float2 bb = *(const float2*)&bias[lane * 2];
    float o0 = fmaf(a0, sc, bb.x);
    float o1 = fmaf(a1, sc, bb.y);
    if (relu) { o0 = fmaxf(o0, 0.f); o1 = fmaxf(o1, 0.f); }
    *(float2*)&out[gw * DIM + lane * 2] = make_float2(o0, o1);
}

// ---------------- launch ------------------------------------------------------
extern "C" void kernel_launch(void* const* d_in, const int* in_sizes, int n_in,
                              void* d_out, int out_size) {
    const float* x  = (const float*)d_in[0];
    const int*   ei = (const int*)  d_in[1];   // [2, E]: src row then dst row
    // d_in[2] = batch_num_nodes (16 equal graphs, contiguous -> output is flat h)
    const float* W1 = (const float*)d_in[3];
    const float* b1 = (const float*)d_in[4];
    const float* W2 = (const float*)d_in[5];
    const float* b2 = (const float*)d_in[6];
    const float* W3 = (const float*)d_in[7];
    const float* b3 = (const float*)d_in[8];
    float* out = (float*)d_out;

    void *pT = nullptr, *pH = nullptr;
    cudaGetSymbolAddress(&pT, g_T);
    cudaGetSymbolAddress(&pH, g_H);
    float* T = (float*)pT;
    float* H = (float*)pH;

    const int nb_nodes = (N_NODES + 255) / 256;
    const int nb_edges = (N_EDGES + 255) / 256;
    const int nb_warp  = (N_NODES * 32 + 255) / 256;   // warp per node (agg)
    const int nb_gemm  = N_NODES / 32;                 // 32 rows per block

    zero_kernel <<<nb_nodes, 256>>>();
    deg_kernel  <<<nb_edges, 256>>>(ei);
    scan1_kernel<<<SCAN_BLOCKS, 1024>>>();
    scan3_kernel<<<SCAN_BLOCKS, 1024>>>();
    fill_kernel <<<nb_edges, 256>>>(ei);

    // layer 1
    gemm_kernel<<<nb_gemm, 256>>>(x, W1, T);
    agg_kernel <<<nb_warp, 256>>>(T, b1, H, 1);
    // layer 2
    gemm_kernel<<<nb_gemm, 256>>>(H, W2, T);
    agg_kernel <<<nb_warp, 256>>>(T, b2, H, 1);
    // layer 3 (no relu), write straight to d_out (unbatch == flat copy)
    gemm_kernel<<<nb_gemm, 256>>>(H, W3, T);
    agg_kernel <<<nb_warp, 256>>>(T, b3, out, 0);
}

// round 5
// speedup vs baseline: 2.2656x; 1.0140x over previous
#include <cuda_runtime.h>
#include <cuda_fp16.h>

#define N_NODES 65536
#define N_EDGES 1048576
#define DIM 64
#define SCAN_BLOCKS 64   // 64 blocks x 1024 threads = 65536

// ---------------- scratch (static device allocations; no cudaMalloc) ----------
__device__ int     g_deg_out[N_NODES];
__device__ int     g_deg_in [N_NODES];
__device__ float   g_rs_out [N_NODES];
__device__ float   g_rs_in  [N_NODES];
__device__ int     g_row_off[N_NODES + 1];
__device__ int     g_cursor [N_NODES];
__device__ int     g_blk    [SCAN_BLOCKS];
__device__ int     g_csr_src[N_EDGES];
__device__ __half2 g_T[N_NODES * DIM / 2];  // post-GEMM gather source (fp16!)
__device__ float   g_H[N_NODES * DIM];      // inter-layer hidden buffer (fp32)

// ---------------- setup kernels ----------------------------------------------
__global__ void zero_kernel() {
    int i = blockIdx.x * blockDim.x + threadIdx.x;
    if (i < N_NODES) { g_deg_out[i] = 0; g_deg_in[i] = 0; }
}

__global__ void deg_kernel(const int* __restrict__ ei) {
    int e = blockIdx.x * blockDim.x + threadIdx.x;
    if (e < N_EDGES) {
        atomicAdd(&g_deg_out[ei[e]], 1);
        atomicAdd(&g_deg_in [ei[N_EDGES + e]], 1);
    }
}

// -------- parallel exclusive scan of g_deg_in -> g_row_off --------------------
// S1: block-local scan (1024 elems/block), write local-exclusive + block total
__global__ void scan1_kernel() {
    __shared__ int sm[1024];
    int t   = threadIdx.x;
    int gid = blockIdx.x * 1024 + t;
    int v = g_deg_in[gid];
    sm[t] = v;
    __syncthreads();
#pragma unroll
    for (int off = 1; off < 1024; off <<= 1) {
        int u = (t >= off) ? sm[t - off] : 0;
        __syncthreads();
        sm[t] += u;
        __syncthreads();
    }
    g_row_off[gid] = sm[t] - v;               // local exclusive prefix
    if (t == 1023) g_blk[blockIdx.x] = sm[1023];
}

// S2+S3 fused: PARALLEL block-offset (masked tree reduction over g_blk),
// finalize row_off, seed cursor, compute rsqrt factors.
__global__ void scan3_kernel() {
    __shared__ int red[SCAN_BLOCKS];
    int t = threadIdx.x;
    int b = blockIdx.x;
    if (t < SCAN_BLOCKS) red[t] = (t < b) ? g_blk[t] : 0;   // parallel LDGs
    __syncthreads();
#pragma unroll
    for (int off = SCAN_BLOCKS / 2; off > 0; off >>= 1) {
        if (t < off) red[t] += red[t + off];
        __syncthreads();
    }
    int off_sh = red[0];
    if (t == 0 && b == 0) g_row_off[N_NODES] = N_EDGES;

    int gid = b * 1024 + t;
    int ro = g_row_off[gid] + off_sh;
    g_row_off[gid] = ro;
    g_cursor [gid] = ro;                      // fill uses cursor as write position
    g_rs_out[gid] = rsqrtf(fmaxf((float)g_deg_out[gid], 1.0f));
    g_rs_in [gid] = rsqrtf(fmaxf((float)g_deg_in [gid], 1.0f));
}

__global__ void fill_kernel(const int* __restrict__ ei) {
    int e = blockIdx.x * blockDim.x + threadIdx.x;
    if (e < N_EDGES) {
        int d = ei[N_EDGES + e];
        int p = atomicAdd(&g_cursor[d], 1);   // cursor pre-seeded with row_off
        g_csr_src[p] = ei[e];
    }
}

// ---------------- per-layer kernels -------------------------------------------
// T[n,:] = half( (x[n,:] @ W) * rs_out[n] )
// 256 threads = 8 warps; 4 rows per warp -> 32 rows per block.
// W staged in smem (one LDS.64 per k amortized over 4 rows);
// x staged DUPLICATED as {v,v} so the broadcast operand feeds fma.rn.f32x2 directly.
__global__ void __launch_bounds__(256) gemm_kernel(const float* __restrict__ x,
                                                   const float* __restrict__ W,
                                                   __half2* __restrict__ out) {
    __shared__ float  Ws[DIM * DIM];       // 16KB
    __shared__ float2 Xs[32 * DIM];        // 16KB (x duplicated per element)
    int tid = threadIdx.x;
    int blockRow = blockIdx.x * 32;

#pragma unroll
    for (int i = tid; i < DIM * DIM; i += 256) Ws[i] = W[i];
#pragma unroll
    for (int i = tid; i < 32 * DIM; i += 256) {
        float v = x[blockRow * DIM + i];
        Xs[i] = make_float2(v, v);
    }
    __syncthreads();

    int warp = tid >> 5, lane = tid & 31;
    int r0 = warp * 4;                     // block-local row base

    const unsigned long long* X0 = (const unsigned long long*)&Xs[(r0 + 0) * DIM];
    const unsigned long long* X1 = (const unsigned long long*)&Xs[(r0 + 1) * DIM];
    const unsigned long long* X2 = (const unsigned long long*)&Xs[(r0 + 2) * DIM];
    const unsigned long long* X3 = (const unsigned long long*)&Xs[(r0 + 3) * DIM];

    unsigned long long a0 = 0ull, a1 = 0ull, a2 = 0ull, a3 = 0ull;
#pragma unroll
    for (int k = 0; k < DIM; k++) {
        unsigned long long w2 =
            *(const unsigned long long*)&Ws[k * DIM + lane * 2];  // LDS.64, conflict-free
        asm("fma.rn.f32x2 %0, %1, %2, %0;" : "+l"(a0) : "l"(X0[k]), "l"(w2));
        asm("fma.rn.f32x2 %0, %1, %2, %0;" : "+l"(a1) : "l"(X1[k]), "l"(w2));
        asm("fma.rn.f32x2 %0, %1, %2, %0;" : "+l"(a2) : "l"(X2[k]), "l"(w2));
        asm("fma.rn.f32x2 %0, %1, %2, %0;" : "+l"(a3) : "l"(X3[k]), "l"(w2));
    }

    int row = blockRow + r0;
    unsigned long long acc[4] = {a0, a1, a2, a3};
#pragma unroll
    for (int r = 0; r < 4; r++) {
        float2 a = *(float2*)&acc[r];
        float s = g_rs_out[row + r];
        out[(row + r) * (DIM / 2) + lane] =
            __floats2half2_rn(a.x * s, a.y * s);   // quantize gather source to fp16
    }
}

// out[n,:] = act( rs_in[n] * sum_{e in CSR[n]} T[src_e,:] + b )   (warp per node)
// T is half2 (128B per node row per warp); accumulation in fp32.
__global__ void agg_kernel(const __half2* __restrict__ t,
                           const float* __restrict__ bias,
                           float* __restrict__ out, int relu) {
    int tid  = threadIdx.x;
    int gw   = (blockIdx.x * 256 + tid) >> 5;
    int lane = tid & 31;
    if (gw >= N_NODES) return;

    int beg = g_row_off[gw], end = g_row_off[gw + 1];
    float a0 = 0.f, a1 = 0.f;
    int e = beg;
    for (; e + 4 <= end; e += 4) {                 // 4-way unroll for MLP
        int s0 = g_csr_src[e];
        int s1 = g_csr_src[e + 1];
        int s2 = g_csr_src[e + 2];
        int s3 = g_csr_src[e + 3];
        float2 v0 = __half22float2(t[s0 * (DIM / 2) + lane]);
        float2 v1 = __half22float2(t[s1 * (DIM / 2) + lane]);
        float2 v2 = __half22float2(t[s2 * (DIM / 2) + lane]);
        float2 v3 = __half22float2(t[s3 * (DIM / 2) + lane]);
        a0 += (v0.x + v1.x) + (v2.x + v3.x);
        a1 += (v0.y + v1.y) + (v2.y + v3.y);
    }
    for (; e < end; e++) {
        int s0 = g_csr_src[e];
        float2 v = __half22float2(t[s0 * (DIM / 2) + lane]);
        a0 += v.x; a1 += v.y;
    }
    float sc = g_rs_in[gw];
    float2 bb = *(const float2*)&bias[lane * 2];
    float o0 = fmaf(a0, sc, bb.x);
    float o1 = fmaf(a1, sc, bb.y);
    if (relu) { o0 = fmaxf(o0, 0.f); o1 = fmaxf(o1, 0.f); }
    *(float2*)&out[gw * DIM + lane * 2] = make_float2(o0, o1);
}

// ---------------- launch ------------------------------------------------------
extern "C" void kernel_launch(void* const* d_in, const int* in_sizes, int n_in,
                              void* d_out, int out_size) {
    const float* x  = (const float*)d_in[0];
    const int*   ei = (const int*)  d_in[1];   // [2, E]: src row then dst row
    // d_in[2] = batch_num_nodes (16 equal graphs, contiguous -> output is flat h)
    const float* W1 = (const float*)d_in[3];
    const float* b1 = (const float*)d_in[4];
    const float* W2 = (const float*)d_in[5];
    const float* b2 = (const float*)d_in[6];
    const float* W3 = (const float*)d_in[7];
    const float* b3 = (const float*)d_in[8];
    float* out = (float*)d_out;

    void *pT = nullptr, *pH = nullptr;
    cudaGetSymbolAddress(&pT, g_T);
    cudaGetSymbolAddress(&pH, g_H);
    __half2* T = (__half2*)pT;
    float*   H = (float*)pH;

    const int nb_nodes = (N_NODES + 255) / 256;
    const int nb_edges = (N_EDGES + 255) / 256;
    const int nb_warp  = (N_NODES * 32 + 255) / 256;   // warp per node (agg)
    const int nb_gemm  = N_NODES / 32;                 // 32 rows per block

    zero_kernel <<<nb_nodes, 256>>>();
    deg_kernel  <<<nb_edges, 256>>>(ei);
    scan1_kernel<<<SCAN_BLOCKS, 1024>>>();
    scan3_kernel<<<SCAN_BLOCKS, 1024>>>();
    fill_kernel <<<nb_edges, 256>>>(ei);

    // layer 1
    gemm_kernel<<<nb_gemm, 256>>>(x, W1, T);
    agg_kernel <<<nb_warp, 256>>>(T, b1, H, 1);
    // layer 2
    gemm_kernel<<<nb_gemm, 256>>>(H, W2, T);
    agg_kernel <<<nb_warp, 256>>>(T, b2, H, 1);
    // layer 3 (no relu), write straight to d_out (unbatch == flat copy)
    gemm_kernel<<<nb_gemm, 256>>>(H, W3, T);
    agg_kernel <<<nb_warp, 256>>>(T, b3, out, 0);
}

// round 6
// speedup vs baseline: 2.2761x; 1.0046x over previous
#include <cuda_runtime.h>
#include <cuda_fp16.h>

#define N_NODES 65536
#define N_EDGES 1048576
#define DIM 64
#define SCAN_BLOCKS 64   // 64 blocks x 1024 threads = 65536

// ---------------- scratch (static device allocations; no cudaMalloc) ----------
__device__ int     g_deg_out[N_NODES];
__device__ int     g_deg_in [N_NODES];
__device__ float   g_rs_out [N_NODES];
__device__ float   g_rs_in  [N_NODES];
__device__ int     g_row_off[N_NODES + 1];
__device__ int     g_cursor [N_NODES];
__device__ int     g_blk    [SCAN_BLOCKS];
__device__ int     g_csr_src[N_EDGES];
__device__ __half2 g_T[N_NODES * DIM / 2];  // post-GEMM gather source (fp16)
__device__ float   g_H[N_NODES * DIM];      // inter-layer hidden buffer (fp32)

// ---------------- setup kernels ----------------------------------------------
__global__ void zero_kernel() {
    int i = blockIdx.x * blockDim.x + threadIdx.x;
    if (i < N_NODES) { g_deg_out[i] = 0; g_deg_in[i] = 0; }
}

__global__ void deg_kernel(const int* __restrict__ ei) {
    int e = blockIdx.x * blockDim.x + threadIdx.x;
    if (e < N_EDGES) {
        atomicAdd(&g_deg_out[ei[e]], 1);
        atomicAdd(&g_deg_in [ei[N_EDGES + e]], 1);
    }
}

// -------- parallel exclusive scan of g_deg_in -> g_row_off --------------------
__global__ void scan1_kernel() {
    __shared__ int sm[1024];
    int t   = threadIdx.x;
    int gid = blockIdx.x * 1024 + t;
    int v = g_deg_in[gid];
    sm[t] = v;
    __syncthreads();
#pragma unroll
    for (int off = 1; off < 1024; off <<= 1) {
        int u = (t >= off) ? sm[t - off] : 0;
        __syncthreads();
        sm[t] += u;
        __syncthreads();
    }
    g_row_off[gid] = sm[t] - v;               // local exclusive prefix
    if (t == 1023) g_blk[blockIdx.x] = sm[1023];
}

// S2+S3 fused: parallel block-offset reduction, finalize row_off, seed cursor,
// compute rsqrt factors.
__global__ void scan3_kernel() {
    __shared__ int red[SCAN_BLOCKS];
    int t = threadIdx.x;
    int b = blockIdx.x;
    if (t < SCAN_BLOCKS) red[t] = (t < b) ? g_blk[t] : 0;
    __syncthreads();
#pragma unroll
    for (int off = SCAN_BLOCKS / 2; off > 0; off >>= 1) {
        if (t < off) red[t] += red[t + off];
        __syncthreads();
    }
    int off_sh = red[0];
    if (t == 0 && b == 0) g_row_off[N_NODES] = N_EDGES;

    int gid = b * 1024 + t;
    int ro = g_row_off[gid] + off_sh;
    g_row_off[gid] = ro;
    g_cursor [gid] = ro;
    g_rs_out[gid] = rsqrtf(fmaxf((float)g_deg_out[gid], 1.0f));
    g_rs_in [gid] = rsqrtf(fmaxf((float)g_deg_in [gid], 1.0f));
}

__global__ void fill_kernel(const int* __restrict__ ei) {
    int e = blockIdx.x * blockDim.x + threadIdx.x;
    if (e < N_EDGES) {
        int d = ei[N_EDGES + e];
        int p = atomicAdd(&g_cursor[d], 1);
        g_csr_src[p] = ei[e];
    }
}

// ---------------- per-layer kernels -------------------------------------------
// T[n,:] = half( (x[n,:] @ W) * rs_out[n] )  — 4 rows/warp, f32x2 packed FMA.
__global__ void __launch_bounds__(256) gemm_kernel(const float* __restrict__ x,
                                                   const float* __restrict__ W,
                                                   __half2* __restrict__ out) {
    __shared__ float  Ws[DIM * DIM];       // 16KB
    __shared__ float2 Xs[32 * DIM];        // 16KB (x duplicated per element)
    int tid = threadIdx.x;
    int blockRow = blockIdx.x * 32;

#pragma unroll
    for (int i = tid; i < DIM * DIM; i += 256) Ws[i] = W[i];
#pragma unroll
    for (int i = tid; i < 32 * DIM; i += 256) {
        float v = x[blockRow * DIM + i];
        Xs[i] = make_float2(v, v);
    }
    __syncthreads();

    int warp = tid >> 5, lane = tid & 31;
    int r0 = warp * 4;

    const unsigned long long* X0 = (const unsigned long long*)&Xs[(r0 + 0) * DIM];
    const unsigned long long* X1 = (const unsigned long long*)&Xs[(r0 + 1) * DIM];
    const unsigned long long* X2 = (const unsigned long long*)&Xs[(r0 + 2) * DIM];
    const unsigned long long* X3 = (const unsigned long long*)&Xs[(r0 + 3) * DIM];

    unsigned long long a0 = 0ull, a1 = 0ull, a2 = 0ull, a3 = 0ull;
#pragma unroll
    for (int k = 0; k < DIM; k++) {
        unsigned long long w2 =
            *(const unsigned long long*)&Ws[k * DIM + lane * 2];
        asm("fma.rn.f32x2 %0, %1, %2, %0;" : "+l"(a0) : "l"(X0[k]), "l"(w2));
        asm("fma.rn.f32x2 %0, %1, %2, %0;" : "+l"(a1) : "l"(X1[k]), "l"(w2));
        asm("fma.rn.f32x2 %0, %1, %2, %0;" : "+l"(a2) : "l"(X2[k]), "l"(w2));
        asm("fma.rn.f32x2 %0, %1, %2, %0;" : "+l"(a3) : "l"(X3[k]), "l"(w2));
    }

    int row = blockRow + r0;
    unsigned long long acc[4] = {a0, a1, a2, a3};
#pragma unroll
    for (int r = 0; r < 4; r++) {
        float2 a = *(float2*)&acc[r];
        float s = g_rs_out[row + r];
        out[(row + r) * (DIM / 2) + lane] = __floats2half2_rn(a.x * s, a.y * s);
    }
}

// out[n,:] = act( rs_in[n] * sum_{e in CSR[n]} T[src_e,:] + b )   (warp per node)
// Indices fetched 32-wide per lane, broadcast via shfl -> all gathers independent
// (MLP = degree). Each gather = exactly one 128B line. fp32 accumulation.
__global__ void __launch_bounds__(256) agg_kernel(const __half2* __restrict__ t,
                                                  const float* __restrict__ bias,
                                                  float* __restrict__ out, int relu) {
    int tid  = threadIdx.x;
    int gw   = (blockIdx.x * 256 + tid) >> 5;
    int lane = tid & 31;
    if (gw >= N_NODES) return;

    int beg = g_row_off[gw], end = g_row_off[gw + 1];
    float a0 = 0.f, a1 = 0.f;

    for (int base = beg; base < end; base += 32) {
        int n = end - base;
        if (n > 32) n = 32;
        int myidx = (base + lane < end) ? g_csr_src[base + lane] : 0;

        int j = 0;
        for (; j + 4 <= n; j += 4) {
            int s0 = __shfl_sync(0xffffffffu, myidx, j + 0);
            int s1 = __shfl_sync(0xffffffffu, myidx, j + 1);
            int s2 = __shfl_sync(0xffffffffu, myidx, j + 2);
            int s3 = __shfl_sync(0xffffffffu, myidx, j + 3);
            float2 v0 = __half22float2(t[s0 * (DIM / 2) + lane]);
            float2 v1 = __half22float2(t[s1 * (DIM / 2) + lane]);
            float2 v2 = __half22float2(t[s2 * (DIM / 2) + lane]);
            float2 v3 = __half22float2(t[s3 * (DIM / 2) + lane]);
            a0 += (v0.x + v1.x) + (v2.x + v3.x);
            a1 += (v0.y + v1.y) + (v2.y + v3.y);
        }
        for (; j < n; j++) {
            int s = __shfl_sync(0xffffffffu, myidx, j);
            float2 v = __half22float2(t[s * (DIM / 2) + lane]);
            a0 += v.x; a1 += v.y;
        }
    }

    float sc = g_rs_in[gw];
    float2 bb = *(const float2*)&bias[lane * 2];
    float o0 = fmaf(a0, sc, bb.x);
    float o1 = fmaf(a1, sc, bb.y);
    if (relu) { o0 = fmaxf(o0, 0.f); o1 = fmaxf(o1, 0.f); }
    *(float2*)&out[gw * DIM + lane * 2] = make_float2(o0, o1);
}

// ---------------- launch ------------------------------------------------------
extern "C" void kernel_launch(void* const* d_in, const int* in_sizes, int n_in,
                              void* d_out, int out_size) {
    const float* x  = (const float*)d_in[0];
    const int*   ei = (const int*)  d_in[1];   // [2, E]: src row then dst row
    const float* W1 = (const float*)d_in[3];
    const float* b1 = (const float*)d_in[4];
    const float* W2 = (const float*)d_in[5];
    const float* b2 = (const float*)d_in[6];
    const float* W3 = (const float*)d_in[7];
    const float* b3 = (const float*)d_in[8];
    float* out = (float*)d_out;

    void *pT = nullptr, *pH = nullptr;
    cudaGetSymbolAddress(&pT, g_T);
    cudaGetSymbolAddress(&pH, g_H);
    __half2* T = (__half2*)pT;
    float*   H = (float*)pH;

    const int nb_nodes = (N_NODES + 255) / 256;
    const int nb_edges = (N_EDGES + 255) / 256;
    const int nb_warp  = (N_NODES * 32 + 255) / 256;   // warp per node (agg)
    const int nb_gemm  = N_NODES / 32;                 // 32 rows per block

    zero_kernel <<<nb_nodes, 256>>>();
    deg_kernel  <<<nb_edges, 256>>>(ei);
    scan1_kernel<<<SCAN_BLOCKS, 1024>>>();
    scan3_kernel<<<SCAN_BLOCKS, 1024>>>();
    fill_kernel <<<nb_edges, 256>>>(ei);

    // layer 1
    gemm_kernel<<<nb_gemm, 256>>>(x, W1, T);
    agg_kernel <<<nb_warp, 256>>>(T, b1, H, 1);
    // layer 2
    gemm_kernel<<<nb_gemm, 256>>>(H, W2, T);
    agg_kernel <<<nb_warp, 256>>>(T, b2, H, 1);
    // layer 3 (no relu), write straight to d_out (unbatch == flat copy)
    gemm_kernel<<<nb_gemm, 256>>>(H, W3, T);
    agg_kernel <<<nb_warp, 256>>>(T, b3, out, 0);
}